// round 5
// baseline (speedup 1.0000x reference)
#include <cuda_runtime.h>
#include <cuda_bf16.h>
#include <cstdint>

// ---------------------------------------------------------------------------
// Fused sparse-conv block via mma.sync bf16 hi/lo 3-pass split (~fp32 acc).
// R5: 8 warps/CTA (32x32 warp tiles), 2 CTAs/SM -> 16 warps/SM for latency
//     hiding (R4 was 8 warps/SM, issue=28.5%, tensor=55%).
// CTA tile: M=128 x N=64. Warp (wy,wx): rows wy*32+[0,32), cols wx*32+[0,32).
// ---------------------------------------------------------------------------

typedef __nv_bfloat16 bf16;
#define N_CH 64
#define MAXP 250048

__device__ bf16 g_fhi[(size_t)MAXP * N_CH];
__device__ bf16 g_flo[(size_t)MAXP * N_CH];
__device__ bf16 g_ahi[(size_t)MAXP * N_CH];
__device__ bf16 g_alo[(size_t)MAXP * N_CH];
__device__ bf16 g_bhi[(size_t)MAXP * N_CH];
__device__ bf16 g_blo[(size_t)MAXP * N_CH];
__device__ bf16 g_whi[4 * 27 * 64 * 64];
__device__ bf16 g_wlo[4 * 27 * 64 * 64];

// ---- smem layout. 128B row pitch + XOR-16B-chunk swizzle (conflict-free).
#define OFF_BIAS  0                    // 64 floats = 256
#define OFF_NBS   256                  // 128*27 ints = 13824 -> 14080
#define OFF_BUF   14336                // 1024-aligned
#define A_HI      0                    // 128 rows * 128B = 16384
#define A_LO      16384
#define B_HI      32768                // 64 rows * 128B = 8192
#define B_LO      40960
#define STAGE_SZ  49152
#define SMEM_TOTAL (OFF_BUF + 2 * STAGE_SZ)   // 112640 -> 2 CTAs/SM

// ---------------- PTX helpers ----------------
__device__ __forceinline__ void cp16(void* dst, const void* src) {
    uint32_t d;
    asm("{ .reg .u64 t; cvta.to.shared.u64 t, %1; cvt.u32.u64 %0, t; }" : "=r"(d) : "l"(dst));
    asm volatile("cp.async.ca.shared.global [%0], [%1], 16;" :: "r"(d), "l"(src));
}
__device__ __forceinline__ void zero16(void* dst) {
    *(float4*)dst = make_float4(0.f, 0.f, 0.f, 0.f);
}
#define CP_COMMIT() asm volatile("cp.async.commit_group;" ::: "memory")
#define CP_WAIT1()  asm volatile("cp.async.wait_group 1;" ::: "memory")
#define CP_WAIT0()  asm volatile("cp.async.wait_group 0;" ::: "memory")

__device__ __forceinline__ void mma_bf16(float* c, const uint32_t* a, const uint32_t* b) {
    asm volatile(
        "mma.sync.aligned.m16n8k16.row.col.f32.bf16.bf16.f32 "
        "{%0,%1,%2,%3}, {%4,%5,%6,%7}, {%8,%9}, {%0,%1,%2,%3};"
        : "+f"(c[0]), "+f"(c[1]), "+f"(c[2]), "+f"(c[3])
        : "r"(a[0]), "r"(a[1]), "r"(a[2]), "r"(a[3]), "r"(b[0]), "r"(b[1]));
}

// ---------------- prep kernels ----------------
__global__ void prep_weights(const float* __restrict__ W0, const float* __restrict__ W1,
                             const float* __restrict__ W2, const float* __restrict__ W3,
                             bf16* __restrict__ whi, bf16* __restrict__ wlo) {
    int layer = blockIdx.y;
    int i = blockIdx.x * 256 + threadIdx.x;          // over 27*64*64
    if (i >= 27 * 4096) return;
    const float* W = (layer == 0) ? W0 : (layer == 1) ? W1 : (layer == 2) ? W2 : W3;
    int k = i >> 12, n = (i >> 6) & 63, kk = i & 63;
    float w = W[((size_t)k * 64 + kk) * 64 + n];     // store [k][n][kk] (B col-major)
    bf16 h = __float2bfloat16(w);
    size_t o = (size_t)layer * 27 * 4096 + i;
    whi[o] = h;
    wlo[o] = __float2bfloat16(w - __bfloat162float(h));
}

__global__ void prep_feats(const float* __restrict__ f, bf16* __restrict__ fhi,
                           bf16* __restrict__ flo, int n) {
    int i = blockIdx.x * 256 + threadIdx.x;
    if (i >= n) return;
    float v = f[i];
    bf16 h = __float2bfloat16(v);
    fhi[i] = h;
    flo[i] = __float2bfloat16(v - __bfloat162float(h));
}

// ---------------- main conv kernel ----------------
// MODE 0: h = relu(acc+b)            -> bf16 hi/lo out
// MODE 1: h = (acc+b)*beta + gamma   -> bf16 hi/lo out  (extra = cond [P,128])
// MODE 3: h = relu(acc+b) + extra    -> fp32 out        (extra = feats [P,64])
template <int MODE>
__global__ __launch_bounds__(256, 2) void conv_mma(
    const bf16* __restrict__ xhi, const bf16* __restrict__ xlo,
    const int*  __restrict__ nbr,
    const bf16* __restrict__ whi, const bf16* __restrict__ wlo,
    const float* __restrict__ bias, const float* __restrict__ extra,
    float* __restrict__ outf, bf16* __restrict__ outhi, bf16* __restrict__ outlo,
    int P)
{
    extern __shared__ char smem[];
    const int tid  = threadIdx.x;
    const int wid  = tid >> 5;
    const int lane = tid & 31;
    const int wy   = wid >> 1;        // 0..3 : 32-row slab
    const int wx   = wid & 1;         // 0..1 : 32-col half
    const int rA   = lane >> 2;       // 0..7
    const int cq   = lane & 3;        // 0..3
    const int p0   = blockIdx.x * 128;

    int*   nbs     = (int*)(smem + OFF_NBS);
    float* bias_sm = (float*)(smem + OFF_BIAS);

    if (tid < 64) bias_sm[tid] = bias[tid];
    for (int t = tid; t < 128 * 27; t += 256) {
        int row = t / 27, p = p0 + row;
        nbs[t] = (p < P) ? nbr[(size_t)p * 27 + (t - row * 27)] : -1;
    }
    __syncthreads();

    auto gather = [&](int k, int stg) {
        char* base = smem + OFF_BUF + stg * STAGE_SZ;
        // A: 128 rows x 8 chunks x hi/lo = 2048 chunks
        #pragma unroll
        for (int it = 0; it < 8; ++it) {
            int task = it * 256 + tid;
            int half = task >> 10;
            int rc   = task & 1023;
            int row  = rc >> 3;
            int c    = rc & 7;
            int n    = nbs[row * 27 + k];
            char* dst = base + (half ? A_LO : A_HI) + row * 128 + ((c ^ (row & 7)) << 4);
            if (n >= 0)
                cp16(dst, (half ? xlo : xhi) + (size_t)n * 64 + c * 8);
            else
                zero16(dst);
        }
        // B: 64 rows x 8 chunks x hi/lo = 1024 chunks
        const bf16* wb_hi = whi + (size_t)k * 4096;
        const bf16* wb_lo = wlo + (size_t)k * 4096;
        #pragma unroll
        for (int it = 0; it < 4; ++it) {
            int task = it * 256 + tid;
            int half = task >> 9;
            int rc   = task & 511;
            int row  = rc >> 3;
            int c    = rc & 7;
            char* dst = base + (half ? B_LO : B_HI) + row * 128 + ((c ^ (row & 7)) << 4);
            cp16(dst, (half ? wb_lo : wb_hi) + (size_t)row * 64 + c * 8);
        }
        CP_COMMIT();
    };

    gather(0, 0);
    gather(1, 1);

    float acc[2][4][4];               // [m-tile][n-frag][frag]
    #pragma unroll
    for (int t = 0; t < 2; ++t)
        #pragma unroll
        for (int j = 0; j < 4; ++j)
            #pragma unroll
            for (int q = 0; q < 4; ++q) acc[t][j][q] = 0.f;

    const uint32_t sw = (uint32_t)(rA << 4);   // row&7 == rA for all rows used

    for (int k = 0; k < 27; ++k) {
        const int s = k & 1;
        if (k < 26) CP_WAIT1(); else CP_WAIT0();
        __syncthreads();

        char* base = smem + OFF_BUF + s * STAGE_SZ;
        // warp base rows: A row0 = wy*32 + rA ; B row0 = wx*32 + rA
        const char* Ah = base + A_HI + (wy * 32 + rA) * 128;
        const char* Al = base + A_LO + (wy * 32 + rA) * 128;
        const char* Bh = base + B_HI + (wx * 32 + rA) * 128;
        const char* Bl = base + B_LO + (wx * 32 + rA) * 128;

        #pragma unroll
        for (int ks = 0; ks < 4; ++ks) {
            const uint32_t c0 = (uint32_t)(ks * 32 + cq * 4) ^ sw;       // k-lo
            const uint32_t c1 = (uint32_t)(ks * 32 + 16 + cq * 4) ^ sw;  // k-hi

            uint32_t ah[2][4], al[2][4];
            #pragma unroll
            for (int t = 0; t < 2; ++t) {
                const char* ph = Ah + t * 2048;   // +16 rows
                const char* pl = Al + t * 2048;
                ah[t][0] = *(const uint32_t*)(ph + c0);
                ah[t][1] = *(const uint32_t*)(ph + 1024 + c0);  // +8 rows
                ah[t][2] = *(const uint32_t*)(ph + c1);
                ah[t][3] = *(const uint32_t*)(ph + 1024 + c1);
                al[t][0] = *(const uint32_t*)(pl + c0);
                al[t][1] = *(const uint32_t*)(pl + 1024 + c0);
                al[t][2] = *(const uint32_t*)(pl + c1);
                al[t][3] = *(const uint32_t*)(pl + 1024 + c1);
            }
            uint32_t bh[4][2], bl[4][2];
            #pragma unroll
            for (int j = 0; j < 4; ++j) {
                const char* ph = Bh + j * 1024;   // +8 n-rows
                const char* pl = Bl + j * 1024;
                bh[j][0] = *(const uint32_t*)(ph + c0);
                bh[j][1] = *(const uint32_t*)(ph + c1);
                bl[j][0] = *(const uint32_t*)(pl + c0);
                bl[j][1] = *(const uint32_t*)(pl + c1);
            }
            #pragma unroll
            for (int t = 0; t < 2; ++t)
                #pragma unroll
                for (int j = 0; j < 4; ++j) mma_bf16(acc[t][j], ah[t], bh[j]);
            #pragma unroll
            for (int t = 0; t < 2; ++t)
                #pragma unroll
                for (int j = 0; j < 4; ++j) mma_bf16(acc[t][j], ah[t], bl[j]);
            #pragma unroll
            for (int t = 0; t < 2; ++t)
                #pragma unroll
                for (int j = 0; j < 4; ++j) mma_bf16(acc[t][j], al[t], bh[j]);
        }
        __syncthreads();
        if (k + 2 < 27) gather(k + 2, s);
    }

    // ---------------- epilogue ----------------
    #pragma unroll
    for (int t = 0; t < 2; ++t) {
        #pragma unroll
        for (int half = 0; half < 2; ++half) {
            const int p = p0 + wy * 32 + t * 16 + rA + half * 8;
            if (p >= P) continue;
            #pragma unroll
            for (int j = 0; j < 4; ++j) {
                const int col = wx * 32 + j * 8 + cq * 2;
                float v0 = acc[t][j][half * 2 + 0] + bias_sm[col];
                float v1 = acc[t][j][half * 2 + 1] + bias_sm[col + 1];
                if (MODE == 0) {
                    v0 = fmaxf(v0, 0.f); v1 = fmaxf(v1, 0.f);
                } else if (MODE == 1) {
                    float2 be = *(const float2*)(extra + (size_t)p * 128 + col);
                    float2 ga = *(const float2*)(extra + (size_t)p * 128 + 64 + col);
                    v0 = v0 * be.x + ga.x;
                    v1 = v1 * be.y + ga.y;
                } else { // MODE 3
                    float2 rs = *(const float2*)(extra + (size_t)p * 64 + col);
                    v0 = fmaxf(v0, 0.f) + rs.x;
                    v1 = fmaxf(v1, 0.f) + rs.y;
                }
                if (MODE == 3) {
                    *(float2*)(outf + (size_t)p * 64 + col) = make_float2(v0, v1);
                } else {
                    bf16 h0 = __float2bfloat16(v0), h1 = __float2bfloat16(v1);
                    bf16 l0 = __float2bfloat16(v0 - __bfloat162float(h0));
                    bf16 l1 = __float2bfloat16(v1 - __bfloat162float(h1));
                    uint32_t hp = (uint32_t)__bfloat16_as_ushort(h0) |
                                  ((uint32_t)__bfloat16_as_ushort(h1) << 16);
                    uint32_t lp = (uint32_t)__bfloat16_as_ushort(l0) |
                                  ((uint32_t)__bfloat16_as_ushort(l1) << 16);
                    *(uint32_t*)(outhi + (size_t)p * 64 + col) = hp;
                    *(uint32_t*)(outlo + (size_t)p * 64 + col) = lp;
                }
            }
        }
    }
}

// ---------------- launch ----------------
extern "C" void kernel_launch(void* const* d_in, const int* in_sizes, int n_in,
                              void* d_out, int out_size)
{
    const float* feats = (const float*)d_in[0];
    const float* cond  = (const float*)d_in[1];
    const float* W1a   = (const float*)d_in[2];
    const float* b1a   = (const float*)d_in[3];
    const float* W1b   = (const float*)d_in[4];
    const float* b1b   = (const float*)d_in[5];
    const float* W2a   = (const float*)d_in[6];
    const float* b2a   = (const float*)d_in[7];
    const float* W2b   = (const float*)d_in[8];
    const float* b2b   = (const float*)d_in[9];
    const int*   nbr   = (const int*)d_in[10];

    int P = in_sizes[0] / N_CH;
    float* out = (float*)d_out;

    bf16 *fhi, *flo, *ahi, *alo, *bhi, *blo, *whi, *wlo;
    cudaGetSymbolAddress((void**)&fhi, g_fhi);
    cudaGetSymbolAddress((void**)&flo, g_flo);
    cudaGetSymbolAddress((void**)&ahi, g_ahi);
    cudaGetSymbolAddress((void**)&alo, g_alo);
    cudaGetSymbolAddress((void**)&bhi, g_bhi);
    cudaGetSymbolAddress((void**)&blo, g_blo);
    cudaGetSymbolAddress((void**)&whi, g_whi);
    cudaGetSymbolAddress((void**)&wlo, g_wlo);

    cudaFuncSetAttribute(conv_mma<0>, cudaFuncAttributeMaxDynamicSharedMemorySize, SMEM_TOTAL);
    cudaFuncSetAttribute(conv_mma<1>, cudaFuncAttributeMaxDynamicSharedMemorySize, SMEM_TOTAL);
    cudaFuncSetAttribute(conv_mma<3>, cudaFuncAttributeMaxDynamicSharedMemorySize, SMEM_TOTAL);

    {
        dim3 g((27 * 4096 + 255) / 256, 4);
        prep_weights<<<g, 256>>>(W1a, W1b, W2a, W2b, whi, wlo);
    }
    prep_feats<<<(P * N_CH + 255) / 256, 256>>>(feats, fhi, flo, P * N_CH);

    const size_t LW = (size_t)27 * 4096;
    int grid = (P + 127) / 128;
    conv_mma<0><<<grid, 256, SMEM_TOTAL>>>(fhi, flo, nbr, whi + 0 * LW, wlo + 0 * LW,
                                           b1a, nullptr, nullptr, ahi, alo, P);
    conv_mma<1><<<grid, 256, SMEM_TOTAL>>>(ahi, alo, nbr, whi + 1 * LW, wlo + 1 * LW,
                                           b1b, cond, nullptr, bhi, blo, P);
    conv_mma<0><<<grid, 256, SMEM_TOTAL>>>(bhi, blo, nbr, whi + 2 * LW, wlo + 2 * LW,
                                           b2a, nullptr, nullptr, ahi, alo, P);
    conv_mma<3><<<grid, 256, SMEM_TOTAL>>>(ahi, alo, nbr, whi + 3 * LW, wlo + 3 * LW,
                                           b2b, feats, out, nullptr, nullptr, P);
}

// round 6
// speedup vs baseline: 1.1100x; 1.1100x over previous
#include <cuda_runtime.h>
#include <cuda_bf16.h>
#include <cstdint>

// ---------------------------------------------------------------------------
// Fused sparse-conv block via mma.sync bf16 hi/lo 3-pass split (~fp32 acc).
// R6: ldmatrix.x4 fragment loads (32 LDSM vs 128 LDS.32 per warp per tap)
//     to unblock the tensor pipe (R5: tensor=54%, L1=70%, issue=31%).
// CTA tile: M=128 x N=64, 8 warps (32x32 tiles), 2 CTAs/SM.
// ---------------------------------------------------------------------------

typedef __nv_bfloat16 bf16;
#define N_CH 64
#define MAXP 250048

__device__ bf16 g_fhi[(size_t)MAXP * N_CH];
__device__ bf16 g_flo[(size_t)MAXP * N_CH];
__device__ bf16 g_ahi[(size_t)MAXP * N_CH];
__device__ bf16 g_alo[(size_t)MAXP * N_CH];
__device__ bf16 g_bhi[(size_t)MAXP * N_CH];
__device__ bf16 g_blo[(size_t)MAXP * N_CH];
__device__ bf16 g_whi[4 * 27 * 64 * 64];
__device__ bf16 g_wlo[4 * 27 * 64 * 64];

// ---- smem layout. 128B row pitch + XOR-16B-chunk swizzle (conflict-free).
#define OFF_BIAS  0                    // 64 floats
#define OFF_NBS   256                  // 128*27 ints = 13824 -> 14080
#define OFF_BUF   14336                // 1024-aligned
#define A_HI      0                    // 128 rows * 128B
#define A_LO      16384
#define B_HI      32768                // 64 rows * 128B
#define B_LO      40960
#define STAGE_SZ  49152
#define SMEM_TOTAL (OFF_BUF + 2 * STAGE_SZ)   // 112640 -> 2 CTAs/SM

// ---------------- PTX helpers ----------------
__device__ __forceinline__ void cp16(void* dst, const void* src) {
    uint32_t d;
    asm("{ .reg .u64 t; cvta.to.shared.u64 t, %1; cvt.u32.u64 %0, t; }" : "=r"(d) : "l"(dst));
    asm volatile("cp.async.ca.shared.global [%0], [%1], 16;" :: "r"(d), "l"(src));
}
__device__ __forceinline__ void zero16(void* dst) {
    *(float4*)dst = make_float4(0.f, 0.f, 0.f, 0.f);
}
#define CP_COMMIT() asm volatile("cp.async.commit_group;" ::: "memory")
#define CP_WAIT1()  asm volatile("cp.async.wait_group 1;" ::: "memory")
#define CP_WAIT0()  asm volatile("cp.async.wait_group 0;" ::: "memory")

__device__ __forceinline__ void ldsm4(uint32_t* r, uint32_t addr) {
    asm volatile("ldmatrix.sync.aligned.m8n8.x4.shared.b16 {%0,%1,%2,%3}, [%4];"
                 : "=r"(r[0]), "=r"(r[1]), "=r"(r[2]), "=r"(r[3]) : "r"(addr));
}
__device__ __forceinline__ void mma_bf16(float* c, const uint32_t* a, const uint32_t* b) {
    asm volatile(
        "mma.sync.aligned.m16n8k16.row.col.f32.bf16.bf16.f32 "
        "{%0,%1,%2,%3}, {%4,%5,%6,%7}, {%8,%9}, {%0,%1,%2,%3};"
        : "+f"(c[0]), "+f"(c[1]), "+f"(c[2]), "+f"(c[3])
        : "r"(a[0]), "r"(a[1]), "r"(a[2]), "r"(a[3]), "r"(b[0]), "r"(b[1]));
}

// ---------------- prep kernels ----------------
__global__ void prep_weights(const float* __restrict__ W0, const float* __restrict__ W1,
                             const float* __restrict__ W2, const float* __restrict__ W3,
                             bf16* __restrict__ whi, bf16* __restrict__ wlo) {
    int layer = blockIdx.y;
    int i = blockIdx.x * 256 + threadIdx.x;          // over 27*64*64
    if (i >= 27 * 4096) return;
    const float* W = (layer == 0) ? W0 : (layer == 1) ? W1 : (layer == 2) ? W2 : W3;
    int k = i >> 12, n = (i >> 6) & 63, kk = i & 63;
    float w = W[((size_t)k * 64 + kk) * 64 + n];     // store [k][n][kk] (B col-major)
    bf16 h = __float2bfloat16(w);
    size_t o = (size_t)layer * 27 * 4096 + i;
    whi[o] = h;
    wlo[o] = __float2bfloat16(w - __bfloat162float(h));
}

__global__ void prep_feats(const float* __restrict__ f, bf16* __restrict__ fhi,
                           bf16* __restrict__ flo, int n) {
    int i = blockIdx.x * 256 + threadIdx.x;
    if (i >= n) return;
    float v = f[i];
    bf16 h = __float2bfloat16(v);
    fhi[i] = h;
    flo[i] = __float2bfloat16(v - __bfloat162float(h));
}

// ---------------- main conv kernel ----------------
// MODE 0: h = relu(acc+b)            -> bf16 hi/lo out
// MODE 1: h = (acc+b)*beta + gamma   -> bf16 hi/lo out  (extra = cond [P,128])
// MODE 3: h = relu(acc+b) + extra    -> fp32 out        (extra = feats [P,64])
template <int MODE>
__global__ __launch_bounds__(256, 2) void conv_mma(
    const bf16* __restrict__ xhi, const bf16* __restrict__ xlo,
    const int*  __restrict__ nbr,
    const bf16* __restrict__ whi, const bf16* __restrict__ wlo,
    const float* __restrict__ bias, const float* __restrict__ extra,
    float* __restrict__ outf, bf16* __restrict__ outhi, bf16* __restrict__ outlo,
    int P)
{
    extern __shared__ char smem[];
    const uint32_t sb = (uint32_t)__cvta_generic_to_shared(smem);
    const int tid  = threadIdx.x;
    const int wid  = tid >> 5;
    const int lane = tid & 31;
    const int wy   = wid >> 1;        // 0..3 : 32-row slab
    const int wx   = wid & 1;         // 0..1 : 32-col half
    const int rA   = lane >> 2;       // 0..7
    const int cq   = lane & 3;        // 0..3
    const int p0   = blockIdx.x * 128;

    int*   nbs     = (int*)(smem + OFF_NBS);
    float* bias_sm = (float*)(smem + OFF_BIAS);

    if (tid < 64) bias_sm[tid] = bias[tid];
    for (int t = tid; t < 128 * 27; t += 256) {
        int row = t / 27, p = p0 + row;
        nbs[t] = (p < P) ? nbr[(size_t)p * 27 + (t - row * 27)] : -1;
    }
    __syncthreads();

    auto gather = [&](int k, int stg) {
        char* base = smem + OFF_BUF + stg * STAGE_SZ;
        #pragma unroll
        for (int it = 0; it < 8; ++it) {           // A: 2048 chunks
            int task = it * 256 + tid;
            int half = task >> 10;
            int rc   = task & 1023;
            int row  = rc >> 3;
            int c    = rc & 7;
            int n    = nbs[row * 27 + k];
            char* dst = base + (half ? A_LO : A_HI) + row * 128 + ((c ^ (row & 7)) << 4);
            if (n >= 0)
                cp16(dst, (half ? xlo : xhi) + (size_t)n * 64 + c * 8);
            else
                zero16(dst);
        }
        const bf16* wb_hi = whi + (size_t)k * 4096;
        const bf16* wb_lo = wlo + (size_t)k * 4096;
        #pragma unroll
        for (int it = 0; it < 4; ++it) {           // B: 1024 chunks
            int task = it * 256 + tid;
            int half = task >> 9;
            int rc   = task & 511;
            int row  = rc >> 3;
            int c    = rc & 7;
            char* dst = base + (half ? B_LO : B_HI) + row * 128 + ((c ^ (row & 7)) << 4);
            cp16(dst, (half ? wb_lo : wb_hi) + (size_t)row * 64 + c * 8);
        }
        CP_COMMIT();
    };

    gather(0, 0);
    gather(1, 1);

    float acc[2][4][4];               // [m-tile][n-group][frag]
    #pragma unroll
    for (int t = 0; t < 2; ++t)
        #pragma unroll
        for (int j = 0; j < 4; ++j)
            #pragma unroll
            for (int q = 0; q < 4; ++q) acc[t][j][q] = 0.f;

    // ldmatrix lane->address mapping
    const int mm = lane >> 3;         // matrix index 0..3
    const int r8 = lane & 7;
    // A x4: m0=(rows+0,klo) m1=(rows+8,klo) m2=(rows+0,khi) m3=(rows+8,khi)
    const int arow0 = wy * 32 + (mm & 1) * 8 + r8;       // tile t adds t*16
    const int akc   = mm >> 1;                           // k 16B-chunk within k16
    // B x4: m0=(ng+0,klo) m1=(ng+0,khi) m2=(ng+1,klo) m3=(ng+1,khi)
    const int brow0 = wx * 32 + (mm >> 1) * 8 + r8;      // pair q adds q*16
    const int bkc   = mm & 1;

    for (int k = 0; k < 27; ++k) {
        const int s = k & 1;
        if (k < 26) CP_WAIT1(); else CP_WAIT0();
        __syncthreads();

        const uint32_t stg = sb + OFF_BUF + s * STAGE_SZ;

        #pragma unroll
        for (int ks = 0; ks < 4; ++ks) {
            const int ca = ks * 2 + akc;    // A col chunk
            const int cb = ks * 2 + bkc;    // B col chunk

            uint32_t ah[2][4], al[2][4];
            #pragma unroll
            for (int t = 0; t < 2; ++t) {
                const int row = arow0 + t * 16;
                const uint32_t off = (uint32_t)(row * 128 + (((uint32_t)ca ^ (row & 7)) << 4));
                ldsm4(ah[t], stg + A_HI + off);
                ldsm4(al[t], stg + A_LO + off);
            }
            uint32_t bh[2][4], bl[2][4];
            #pragma unroll
            for (int q = 0; q < 2; ++q) {
                const int row = brow0 + q * 16;
                const uint32_t off = (uint32_t)(row * 128 + (((uint32_t)cb ^ (row & 7)) << 4));
                ldsm4(bh[q], stg + B_HI + off);
                ldsm4(bl[q], stg + B_LO + off);
            }
            #pragma unroll
            for (int t = 0; t < 2; ++t)
                #pragma unroll
                for (int j = 0; j < 4; ++j)
                    mma_bf16(acc[t][j], ah[t], &bh[j >> 1][(j & 1) * 2]);
            #pragma unroll
            for (int t = 0; t < 2; ++t)
                #pragma unroll
                for (int j = 0; j < 4; ++j)
                    mma_bf16(acc[t][j], ah[t], &bl[j >> 1][(j & 1) * 2]);
            #pragma unroll
            for (int t = 0; t < 2; ++t)
                #pragma unroll
                for (int j = 0; j < 4; ++j)
                    mma_bf16(acc[t][j], al[t], &bh[j >> 1][(j & 1) * 2]);
        }
        __syncthreads();
        if (k + 2 < 27) gather(k + 2, s);
    }

    // ---------------- epilogue ----------------
    #pragma unroll
    for (int t = 0; t < 2; ++t) {
        #pragma unroll
        for (int half = 0; half < 2; ++half) {
            const int p = p0 + wy * 32 + t * 16 + rA + half * 8;
            if (p >= P) continue;
            #pragma unroll
            for (int j = 0; j < 4; ++j) {
                const int col = wx * 32 + j * 8 + cq * 2;
                float v0 = acc[t][j][half * 2 + 0] + bias_sm[col];
                float v1 = acc[t][j][half * 2 + 1] + bias_sm[col + 1];
                if (MODE == 0) {
                    v0 = fmaxf(v0, 0.f); v1 = fmaxf(v1, 0.f);
                } else if (MODE == 1) {
                    float2 be = *(const float2*)(extra + (size_t)p * 128 + col);
                    float2 ga = *(const float2*)(extra + (size_t)p * 128 + 64 + col);
                    v0 = v0 * be.x + ga.x;
                    v1 = v1 * be.y + ga.y;
                } else { // MODE 3
                    float2 rs = *(const float2*)(extra + (size_t)p * 64 + col);
                    v0 = fmaxf(v0, 0.f) + rs.x;
                    v1 = fmaxf(v1, 0.f) + rs.y;
                }
                if (MODE == 3) {
                    *(float2*)(outf + (size_t)p * 64 + col) = make_float2(v0, v1);
                } else {
                    bf16 h0 = __float2bfloat16(v0), h1 = __float2bfloat16(v1);
                    bf16 l0 = __float2bfloat16(v0 - __bfloat162float(h0));
                    bf16 l1 = __float2bfloat16(v1 - __bfloat162float(h1));
                    uint32_t hp = (uint32_t)__bfloat16_as_ushort(h0) |
                                  ((uint32_t)__bfloat16_as_ushort(h1) << 16);
                    uint32_t lp = (uint32_t)__bfloat16_as_ushort(l0) |
                                  ((uint32_t)__bfloat16_as_ushort(l1) << 16);
                    *(uint32_t*)(outhi + (size_t)p * 64 + col) = hp;
                    *(uint32_t*)(outlo + (size_t)p * 64 + col) = lp;
                }
            }
        }
    }
}

// ---------------- launch ----------------
extern "C" void kernel_launch(void* const* d_in, const int* in_sizes, int n_in,
                              void* d_out, int out_size)
{
    const float* feats = (const float*)d_in[0];
    const float* cond  = (const float*)d_in[1];
    const float* W1a   = (const float*)d_in[2];
    const float* b1a   = (const float*)d_in[3];
    const float* W1b   = (const float*)d_in[4];
    const float* b1b   = (const float*)d_in[5];
    const float* W2a   = (const float*)d_in[6];
    const float* b2a   = (const float*)d_in[7];
    const float* W2b   = (const float*)d_in[8];
    const float* b2b   = (const float*)d_in[9];
    const int*   nbr   = (const int*)d_in[10];

    int P = in_sizes[0] / N_CH;
    float* out = (float*)d_out;

    bf16 *fhi, *flo, *ahi, *alo, *bhi, *blo, *whi, *wlo;
    cudaGetSymbolAddress((void**)&fhi, g_fhi);
    cudaGetSymbolAddress((void**)&flo, g_flo);
    cudaGetSymbolAddress((void**)&ahi, g_ahi);
    cudaGetSymbolAddress((void**)&alo, g_alo);
    cudaGetSymbolAddress((void**)&bhi, g_bhi);
    cudaGetSymbolAddress((void**)&blo, g_blo);
    cudaGetSymbolAddress((void**)&whi, g_whi);
    cudaGetSymbolAddress((void**)&wlo, g_wlo);

    cudaFuncSetAttribute(conv_mma<0>, cudaFuncAttributeMaxDynamicSharedMemorySize, SMEM_TOTAL);
    cudaFuncSetAttribute(conv_mma<1>, cudaFuncAttributeMaxDynamicSharedMemorySize, SMEM_TOTAL);
    cudaFuncSetAttribute(conv_mma<3>, cudaFuncAttributeMaxDynamicSharedMemorySize, SMEM_TOTAL);

    {
        dim3 g((27 * 4096 + 255) / 256, 4);
        prep_weights<<<g, 256>>>(W1a, W1b, W2a, W2b, whi, wlo);
    }
    prep_feats<<<(P * N_CH + 255) / 256, 256>>>(feats, fhi, flo, P * N_CH);

    const size_t LW = (size_t)27 * 4096;
    int grid = (P + 127) / 128;
    conv_mma<0><<<grid, 256, SMEM_TOTAL>>>(fhi, flo, nbr, whi + 0 * LW, wlo + 0 * LW,
                                           b1a, nullptr, nullptr, ahi, alo, P);
    conv_mma<1><<<grid, 256, SMEM_TOTAL>>>(ahi, alo, nbr, whi + 1 * LW, wlo + 1 * LW,
                                           b1b, cond, nullptr, bhi, blo, P);
    conv_mma<0><<<grid, 256, SMEM_TOTAL>>>(bhi, blo, nbr, whi + 2 * LW, wlo + 2 * LW,
                                           b2a, nullptr, nullptr, ahi, alo, P);
    conv_mma<3><<<grid, 256, SMEM_TOTAL>>>(ahi, alo, nbr, whi + 3 * LW, wlo + 3 * LW,
                                           b2b, feats, out, nullptr, nullptr, P);
}

// round 7
// speedup vs baseline: 1.3909x; 1.2530x over previous
#include <cuda_runtime.h>
#include <cuda_fp16.h>
#include <cstdint>

// ---------------------------------------------------------------------------
// Fused sparse-conv block, fp16 2-pass scheme:
//   D = x16 @ Wh + x16 @ Wl   (W = Wh + Wl exact to ~21 bits; only x is
//   quantized to fp16 -> ~2.8e-4 rel per layer, ~2-4e-4 end-to-end)
// R7: -33% HMMA, -33% LDGSTS vs R6; 3-stage cp.async ring -> 1 sync/tap.
// CTA tile: M=128 x N=64, 8 warps (32x32 tiles), 2 CTAs/SM.
// ---------------------------------------------------------------------------

typedef __half fp16;
#define N_CH 64
#define MAXP 250048

__device__ fp16 g_x16[(size_t)MAXP * N_CH];   // feats fp16
__device__ fp16 g_a16[(size_t)MAXP * N_CH];   // activation ping
__device__ fp16 g_b16[(size_t)MAXP * N_CH];   // activation pong
__device__ fp16 g_wh[4 * 27 * 64 * 64];
__device__ fp16 g_wl[4 * 27 * 64 * 64];

// ---- smem layout. 128B row pitch + XOR-16B-chunk swizzle (conflict-free).
#define OFF_BIAS  0                    // 64 floats
#define OFF_NBS   256                  // 128*27 ints = 13824 -> 14080
#define OFF_BUF   14336
#define A_OFF     0                    // 128 rows * 128B = 16384
#define B_HI      16384                // 64 rows * 128B = 8192
#define B_LO      24576
#define STAGE_SZ  32768
#define N_STAGE   3
#define SMEM_TOTAL (OFF_BUF + N_STAGE * STAGE_SZ)   // 112640 -> 2 CTAs/SM

// ---------------- PTX helpers ----------------
__device__ __forceinline__ void cp16b(void* dst, const void* src) {
    uint32_t d;
    asm("{ .reg .u64 t; cvta.to.shared.u64 t, %1; cvt.u32.u64 %0, t; }" : "=r"(d) : "l"(dst));
    asm volatile("cp.async.ca.shared.global [%0], [%1], 16;" :: "r"(d), "l"(src));
}
__device__ __forceinline__ void zero16(void* dst) {
    *(float4*)dst = make_float4(0.f, 0.f, 0.f, 0.f);
}
#define CP_COMMIT() asm volatile("cp.async.commit_group;" ::: "memory")
#define CP_WAIT1()  asm volatile("cp.async.wait_group 1;" ::: "memory")
#define CP_WAIT0()  asm volatile("cp.async.wait_group 0;" ::: "memory")

__device__ __forceinline__ void ldsm4(uint32_t* r, uint32_t addr) {
    asm volatile("ldmatrix.sync.aligned.m8n8.x4.shared.b16 {%0,%1,%2,%3}, [%4];"
                 : "=r"(r[0]), "=r"(r[1]), "=r"(r[2]), "=r"(r[3]) : "r"(addr));
}
__device__ __forceinline__ void mma_fp16(float* c, const uint32_t* a, const uint32_t* b) {
    asm volatile(
        "mma.sync.aligned.m16n8k16.row.col.f32.f16.f16.f32 "
        "{%0,%1,%2,%3}, {%4,%5,%6,%7}, {%8,%9}, {%0,%1,%2,%3};"
        : "+f"(c[0]), "+f"(c[1]), "+f"(c[2]), "+f"(c[3])
        : "r"(a[0]), "r"(a[1]), "r"(a[2]), "r"(a[3]), "r"(b[0]), "r"(b[1]));
}

// ---------------- prep kernels ----------------
__global__ void prep_weights(const float* __restrict__ W0, const float* __restrict__ W1,
                             const float* __restrict__ W2, const float* __restrict__ W3,
                             fp16* __restrict__ wh, fp16* __restrict__ wl) {
    int layer = blockIdx.y;
    int i = blockIdx.x * 256 + threadIdx.x;          // over 27*64*64
    if (i >= 27 * 4096) return;
    const float* W = (layer == 0) ? W0 : (layer == 1) ? W1 : (layer == 2) ? W2 : W3;
    int k = i >> 12, n = (i >> 6) & 63, kk = i & 63;
    float w = W[((size_t)k * 64 + kk) * 64 + n];     // store [k][n][kk] (B col-major)
    fp16 h = __float2half(w);
    size_t o = (size_t)layer * 27 * 4096 + i;
    wh[o] = h;
    wl[o] = __float2half(w - __half2float(h));
}

__global__ void prep_feats(const float* __restrict__ f, fp16* __restrict__ x16, int n) {
    int i = blockIdx.x * 256 + threadIdx.x;
    if (i >= n) return;
    x16[i] = __float2half(f[i]);
}

// ---------------- main conv kernel ----------------
// MODE 0: h = relu(acc+b)            -> fp16 out
// MODE 1: h = (acc+b)*beta + gamma   -> fp16 out  (extra = cond [P,128])
// MODE 3: h = relu(acc+b) + extra    -> fp32 out  (extra = feats [P,64])
template <int MODE>
__global__ __launch_bounds__(256, 2) void conv_mma(
    const fp16* __restrict__ x,
    const int*  __restrict__ nbr,
    const fp16* __restrict__ wh, const fp16* __restrict__ wl,
    const float* __restrict__ bias, const float* __restrict__ extra,
    float* __restrict__ outf, fp16* __restrict__ out16,
    int P)
{
    extern __shared__ char smem[];
    const uint32_t sb = (uint32_t)__cvta_generic_to_shared(smem);
    const int tid  = threadIdx.x;
    const int wid  = tid >> 5;
    const int lane = tid & 31;
    const int wy   = wid >> 1;        // 0..3 : 32-row slab
    const int wx   = wid & 1;         // 0..1 : 32-col half
    const int rA   = lane >> 2;       // 0..7
    const int cq   = lane & 3;        // 0..3
    const int p0   = blockIdx.x * 128;

    int*   nbs     = (int*)(smem + OFF_NBS);
    float* bias_sm = (float*)(smem + OFF_BIAS);

    if (tid < 64) bias_sm[tid] = bias[tid];
    for (int t = tid; t < 128 * 27; t += 256) {
        int row = t / 27, p = p0 + row;
        nbs[t] = (p < P) ? nbr[(size_t)p * 27 + (t - row * 27)] : -1;
    }
    __syncthreads();

    auto gather = [&](int k, int stg) {
        char* base = smem + OFF_BUF + stg * STAGE_SZ;
        // A: 128 rows x 8 chunks = 1024 chunks (single fp16 tensor)
        #pragma unroll
        for (int it = 0; it < 4; ++it) {
            int task = it * 256 + tid;
            int row  = task >> 3;
            int c    = task & 7;
            int n    = nbs[row * 27 + k];
            char* dst = base + A_OFF + row * 128 + ((c ^ (row & 7)) << 4);
            if (n >= 0)
                cp16b(dst, x + (size_t)n * 64 + c * 8);
            else
                zero16(dst);
        }
        // B: Wh + Wl, 64 rows x 8 chunks each = 1024 chunks
        const fp16* wb_h = wh + (size_t)k * 4096;
        const fp16* wb_l = wl + (size_t)k * 4096;
        #pragma unroll
        for (int it = 0; it < 4; ++it) {
            int task = it * 256 + tid;
            int half = task >> 9;
            int rc   = task & 511;
            int row  = rc >> 3;
            int c    = rc & 7;
            char* dst = base + (half ? B_LO : B_HI) + row * 128 + ((c ^ (row & 7)) << 4);
            cp16b(dst, (half ? wb_l : wb_h) + (size_t)row * 64 + c * 8);
        }
        CP_COMMIT();
    };

    gather(0, 0);
    gather(1, 1);

    float acc[2][4][4];               // [m-tile][n-group][frag]
    #pragma unroll
    for (int t = 0; t < 2; ++t)
        #pragma unroll
        for (int j = 0; j < 4; ++j)
            #pragma unroll
            for (int q = 0; q < 4; ++q) acc[t][j][q] = 0.f;

    // ldmatrix lane->address mapping
    const int mm = lane >> 3;         // matrix index 0..3
    const int r8 = lane & 7;
    // A x4: m0=(rows+0,klo) m1=(rows+8,klo) m2=(rows+0,khi) m3=(rows+8,khi)
    const int arow0 = wy * 32 + (mm & 1) * 8 + r8;       // tile t adds t*16
    const int akc   = mm >> 1;
    // B x4: m0=(ng+0,klo) m1=(ng+0,khi) m2=(ng+1,klo) m3=(ng+1,khi)
    const int brow0 = wx * 32 + (mm >> 1) * 8 + r8;      // pair q adds q*16
    const int bkc   = mm & 1;

    for (int k = 0; k < 27; ++k) {
        const int s = k % 3;
        if (k < 26) CP_WAIT1(); else CP_WAIT0();
        __syncthreads();   // single barrier per tap (3-stage ring)

        const uint32_t stg = sb + OFF_BUF + s * STAGE_SZ;

        #pragma unroll
        for (int ks = 0; ks < 4; ++ks) {
            const int ca = ks * 2 + akc;    // A col chunk
            const int cb = ks * 2 + bkc;    // B col chunk

            uint32_t a[2][4];
            #pragma unroll
            for (int t = 0; t < 2; ++t) {
                const int row = arow0 + t * 16;
                const uint32_t off = (uint32_t)(row * 128 + (((uint32_t)ca ^ (row & 7)) << 4));
                ldsm4(a[t], stg + A_OFF + off);
            }
            uint32_t bh[2][4], bl[2][4];
            #pragma unroll
            for (int q = 0; q < 2; ++q) {
                const int row = brow0 + q * 16;
                const uint32_t off = (uint32_t)(row * 128 + (((uint32_t)cb ^ (row & 7)) << 4));
                ldsm4(bh[q], stg + B_HI + off);
                ldsm4(bl[q], stg + B_LO + off);
            }
            #pragma unroll
            for (int t = 0; t < 2; ++t)
                #pragma unroll
                for (int j = 0; j < 4; ++j)
                    mma_fp16(acc[t][j], a[t], &bh[j >> 1][(j & 1) * 2]);
            #pragma unroll
            for (int t = 0; t < 2; ++t)
                #pragma unroll
                for (int j = 0; j < 4; ++j)
                    mma_fp16(acc[t][j], a[t], &bl[j >> 1][(j & 1) * 2]);
        }
        // no second barrier: gather writes stage (k+2)%3 == (k-1)%3, whose
        // readers (tap k-1) all retired before this tap's barrier.
        if (k + 2 < 27) gather(k + 2, (k + 2) % 3);
    }

    // ---------------- epilogue ----------------
    #pragma unroll
    for (int t = 0; t < 2; ++t) {
        #pragma unroll
        for (int half = 0; half < 2; ++half) {
            const int p = p0 + wy * 32 + t * 16 + rA + half * 8;
            if (p >= P) continue;
            #pragma unroll
            for (int j = 0; j < 4; ++j) {
                const int col = wx * 32 + j * 8 + cq * 2;
                float v0 = acc[t][j][half * 2 + 0] + bias_sm[col];
                float v1 = acc[t][j][half * 2 + 1] + bias_sm[col + 1];
                if (MODE == 0) {
                    v0 = fmaxf(v0, 0.f); v1 = fmaxf(v1, 0.f);
                } else if (MODE == 1) {
                    float2 be = *(const float2*)(extra + (size_t)p * 128 + col);
                    float2 ga = *(const float2*)(extra + (size_t)p * 128 + 64 + col);
                    v0 = v0 * be.x + ga.x;
                    v1 = v1 * be.y + ga.y;
                } else { // MODE 3
                    float2 rs = *(const float2*)(extra + (size_t)p * 64 + col);
                    v0 = fmaxf(v0, 0.f) + rs.x;
                    v1 = fmaxf(v1, 0.f) + rs.y;
                }
                if (MODE == 3) {
                    *(float2*)(outf + (size_t)p * 64 + col) = make_float2(v0, v1);
                } else {
                    __half2 hv = __floats2half2_rn(v0, v1);
                    *(__half2*)(out16 + (size_t)p * 64 + col) = hv;
                }
            }
        }
    }
}

// ---------------- launch ----------------
extern "C" void kernel_launch(void* const* d_in, const int* in_sizes, int n_in,
                              void* d_out, int out_size)
{
    const float* feats = (const float*)d_in[0];
    const float* cond  = (const float*)d_in[1];
    const float* W1a   = (const float*)d_in[2];
    const float* b1a   = (const float*)d_in[3];
    const float* W1b   = (const float*)d_in[4];
    const float* b1b   = (const float*)d_in[5];
    const float* W2a   = (const float*)d_in[6];
    const float* b2a   = (const float*)d_in[7];
    const float* W2b   = (const float*)d_in[8];
    const float* b2b   = (const float*)d_in[9];
    const int*   nbr   = (const int*)d_in[10];

    int P = in_sizes[0] / N_CH;
    float* out = (float*)d_out;

    fp16 *x16, *a16, *b16, *wh, *wl;
    cudaGetSymbolAddress((void**)&x16, g_x16);
    cudaGetSymbolAddress((void**)&a16, g_a16);
    cudaGetSymbolAddress((void**)&b16, g_b16);
    cudaGetSymbolAddress((void**)&wh,  g_wh);
    cudaGetSymbolAddress((void**)&wl,  g_wl);

    cudaFuncSetAttribute(conv_mma<0>, cudaFuncAttributeMaxDynamicSharedMemorySize, SMEM_TOTAL);
    cudaFuncSetAttribute(conv_mma<1>, cudaFuncAttributeMaxDynamicSharedMemorySize, SMEM_TOTAL);
    cudaFuncSetAttribute(conv_mma<3>, cudaFuncAttributeMaxDynamicSharedMemorySize, SMEM_TOTAL);

    {
        dim3 g((27 * 4096 + 255) / 256, 4);
        prep_weights<<<g, 256>>>(W1a, W1b, W2a, W2b, wh, wl);
    }
    prep_feats<<<(P * N_CH + 255) / 256, 256>>>(feats, x16, P * N_CH);

    const size_t LW = (size_t)27 * 4096;
    int grid = (P + 127) / 128;
    conv_mma<0><<<grid, 256, SMEM_TOTAL>>>(x16, nbr, wh + 0 * LW, wl + 0 * LW,
                                           b1a, nullptr, nullptr, a16, P);
    conv_mma<1><<<grid, 256, SMEM_TOTAL>>>(a16, nbr, wh + 1 * LW, wl + 1 * LW,
                                           b1b, cond, nullptr, b16, P);
    conv_mma<0><<<grid, 256, SMEM_TOTAL>>>(b16, nbr, wh + 2 * LW, wl + 2 * LW,
                                           b2a, nullptr, nullptr, a16, P);
    conv_mma<3><<<grid, 256, SMEM_TOTAL>>>(a16, nbr, wh + 3 * LW, wl + 3 * LW,
                                           b2b, feats, out, nullptr, P);
}

// round 8
// speedup vs baseline: 2.0833x; 1.4978x over previous
#include <cuda_runtime.h>
#include <cuda_fp16.h>
#include <cstdint>

// ---------------------------------------------------------------------------
// Fused sparse-conv block, single-pass fp16 (x and W both fp16, fp32 acc).
// R8: -50% HMMA vs R7, -25% gather traffic, 4-stage cp.async ring
//     (24KB/stage, same 112640B footprint that held 2 CTAs/SM in R5-R7).
// Error budget: measured R7 x-only quant = 3.7e-5; adding W quant predicted
// ~1e-4 end-to-end vs 1e-3 threshold.
// CTA tile: M=128 x N=64, 8 warps (32x32 tiles), 2 CTAs/SM.
// ---------------------------------------------------------------------------

typedef __half fp16;
#define N_CH 64
#define MAXP 250048

__device__ fp16 g_x16[(size_t)MAXP * N_CH];   // feats fp16
__device__ fp16 g_a16[(size_t)MAXP * N_CH];   // activation ping
__device__ fp16 g_b16[(size_t)MAXP * N_CH];   // activation pong
__device__ fp16 g_wh[4 * 27 * 64 * 64];

// ---- smem layout. 128B row pitch + XOR-16B-chunk swizzle (conflict-free).
#define OFF_BIAS  0                    // 64 floats
#define OFF_NBS   256                  // 128*27 ints = 13824 -> 14080
#define OFF_BUF   14336
#define A_OFF     0                    // 128 rows * 128B = 16384
#define B_OFF     16384                // 64 rows * 128B = 8192
#define STAGE_SZ  24576
#define N_STAGE   4
#define SMEM_TOTAL (OFF_BUF + N_STAGE * STAGE_SZ)   // 112640 -> 2 CTAs/SM

// ---------------- PTX helpers ----------------
__device__ __forceinline__ void cp16b(void* dst, const void* src) {
    uint32_t d;
    asm("{ .reg .u64 t; cvta.to.shared.u64 t, %1; cvt.u32.u64 %0, t; }" : "=r"(d) : "l"(dst));
    asm volatile("cp.async.ca.shared.global [%0], [%1], 16;" :: "r"(d), "l"(src));
}
__device__ __forceinline__ void zero16(void* dst) {
    *(float4*)dst = make_float4(0.f, 0.f, 0.f, 0.f);
}
#define CP_COMMIT() asm volatile("cp.async.commit_group;" ::: "memory")
#define CP_WAIT2()  asm volatile("cp.async.wait_group 2;" ::: "memory")
#define CP_WAIT0()  asm volatile("cp.async.wait_group 0;" ::: "memory")

__device__ __forceinline__ void ldsm4(uint32_t* r, uint32_t addr) {
    asm volatile("ldmatrix.sync.aligned.m8n8.x4.shared.b16 {%0,%1,%2,%3}, [%4];"
                 : "=r"(r[0]), "=r"(r[1]), "=r"(r[2]), "=r"(r[3]) : "r"(addr));
}
__device__ __forceinline__ void mma_fp16(float* c, const uint32_t* a, const uint32_t* b) {
    asm volatile(
        "mma.sync.aligned.m16n8k16.row.col.f32.f16.f16.f32 "
        "{%0,%1,%2,%3}, {%4,%5,%6,%7}, {%8,%9}, {%0,%1,%2,%3};"
        : "+f"(c[0]), "+f"(c[1]), "+f"(c[2]), "+f"(c[3])
        : "r"(a[0]), "r"(a[1]), "r"(a[2]), "r"(a[3]), "r"(b[0]), "r"(b[1]));
}

// ---------------- prep kernels ----------------
__global__ void prep_weights(const float* __restrict__ W0, const float* __restrict__ W1,
                             const float* __restrict__ W2, const float* __restrict__ W3,
                             fp16* __restrict__ wh) {
    int layer = blockIdx.y;
    int i = blockIdx.x * 256 + threadIdx.x;          // over 27*64*64
    if (i >= 27 * 4096) return;
    const float* W = (layer == 0) ? W0 : (layer == 1) ? W1 : (layer == 2) ? W2 : W3;
    int k = i >> 12, n = (i >> 6) & 63, kk = i & 63;
    float w = W[((size_t)k * 64 + kk) * 64 + n];     // store [k][n][kk] (B col-major)
    wh[(size_t)layer * 27 * 4096 + i] = __float2half(w);
}

__global__ void prep_feats(const float* __restrict__ f, fp16* __restrict__ x16, int n) {
    int i = blockIdx.x * 256 + threadIdx.x;
    if (i >= n) return;
    x16[i] = __float2half(f[i]);
}

// ---------------- main conv kernel ----------------
// MODE 0: h = relu(acc+b)            -> fp16 out
// MODE 1: h = (acc+b)*beta + gamma   -> fp16 out  (extra = cond [P,128])
// MODE 3: h = relu(acc+b) + extra    -> fp32 out  (extra = feats [P,64])
template <int MODE>
__global__ __launch_bounds__(256, 2) void conv_mma(
    const fp16* __restrict__ x,
    const int*  __restrict__ nbr,
    const fp16* __restrict__ wh,
    const float* __restrict__ bias, const float* __restrict__ extra,
    float* __restrict__ outf, fp16* __restrict__ out16,
    int P)
{
    extern __shared__ char smem[];
    const uint32_t sb = (uint32_t)__cvta_generic_to_shared(smem);
    const int tid  = threadIdx.x;
    const int wid  = tid >> 5;
    const int lane = tid & 31;
    const int wy   = wid >> 1;        // 0..3 : 32-row slab
    const int wx   = wid & 1;         // 0..1 : 32-col half
    const int rA   = lane >> 2;       // 0..7
    const int cq   = lane & 3;        // 0..3
    const int p0   = blockIdx.x * 128;

    int*   nbs     = (int*)(smem + OFF_NBS);
    float* bias_sm = (float*)(smem + OFF_BIAS);

    if (tid < 64) bias_sm[tid] = bias[tid];
    for (int t = tid; t < 128 * 27; t += 256) {
        int row = t / 27, p = p0 + row;
        nbs[t] = (p < P) ? nbr[(size_t)p * 27 + (t - row * 27)] : -1;
    }
    __syncthreads();

    auto gather = [&](int k, int stg) {
        char* base = smem + OFF_BUF + stg * STAGE_SZ;
        // A: 128 rows x 8 chunks = 1024 chunks
        #pragma unroll
        for (int it = 0; it < 4; ++it) {
            int task = it * 256 + tid;
            int row  = task >> 3;
            int c    = task & 7;
            int n    = nbs[row * 27 + k];
            char* dst = base + A_OFF + row * 128 + ((c ^ (row & 7)) << 4);
            if (n >= 0)
                cp16b(dst, x + (size_t)n * 64 + c * 8);
            else
                zero16(dst);
        }
        // B: 64 rows x 8 chunks = 512 chunks
        const fp16* wb = wh + (size_t)k * 4096;
        #pragma unroll
        for (int it = 0; it < 2; ++it) {
            int task = it * 256 + tid;
            int row  = task >> 3;
            int c    = task & 7;
            char* dst = base + B_OFF + row * 128 + ((c ^ (row & 7)) << 4);
            cp16b(dst, wb + (size_t)row * 64 + c * 8);
        }
        CP_COMMIT();
    };

    gather(0, 0);
    gather(1, 1);
    gather(2, 2);

    float acc[2][4][4];               // [m-tile][n-group][frag]
    #pragma unroll
    for (int t = 0; t < 2; ++t)
        #pragma unroll
        for (int j = 0; j < 4; ++j)
            #pragma unroll
            for (int q = 0; q < 4; ++q) acc[t][j][q] = 0.f;

    // ldmatrix lane->address mapping
    const int mm = lane >> 3;         // matrix index 0..3
    const int r8 = lane & 7;
    const int arow0 = wy * 32 + (mm & 1) * 8 + r8;       // tile t adds t*16
    const int akc   = mm >> 1;
    const int brow0 = wx * 32 + (mm >> 1) * 8 + r8;      // pair q adds q*16
    const int bkc   = mm & 1;

    for (int k = 0; k < 27; ++k) {
        const int s = k & 3;
        if (k < 25) CP_WAIT2(); else CP_WAIT0();
        __syncthreads();   // single barrier per tap (4-stage ring)

        const uint32_t stg = sb + OFF_BUF + s * STAGE_SZ;

        #pragma unroll
        for (int ks = 0; ks < 4; ++ks) {
            const int ca = ks * 2 + akc;
            const int cb = ks * 2 + bkc;

            uint32_t a[2][4];
            #pragma unroll
            for (int t = 0; t < 2; ++t) {
                const int row = arow0 + t * 16;
                const uint32_t off = (uint32_t)(row * 128 + (((uint32_t)ca ^ (row & 7)) << 4));
                ldsm4(a[t], stg + A_OFF + off);
            }
            uint32_t b[2][4];
            #pragma unroll
            for (int q = 0; q < 2; ++q) {
                const int row = brow0 + q * 16;
                const uint32_t off = (uint32_t)(row * 128 + (((uint32_t)cb ^ (row & 7)) << 4));
                ldsm4(b[q], stg + B_OFF + off);
            }
            #pragma unroll
            for (int t = 0; t < 2; ++t)
                #pragma unroll
                for (int j = 0; j < 4; ++j)
                    mma_fp16(acc[t][j], a[t], &b[j >> 1][(j & 1) * 2]);
        }
        // gather writes stage (k+3)%4 == (k-1)%4; its readers (tap k-1)
        // retired before this tap's barrier.
        if (k + 3 < 27) gather(k + 3, (k + 3) & 3);
    }

    // ---------------- epilogue ----------------
    #pragma unroll
    for (int t = 0; t < 2; ++t) {
        #pragma unroll
        for (int half = 0; half < 2; ++half) {
            const int p = p0 + wy * 32 + t * 16 + rA + half * 8;
            if (p >= P) continue;
            #pragma unroll
            for (int j = 0; j < 4; ++j) {
                const int col = wx * 32 + j * 8 + cq * 2;
                float v0 = acc[t][j][half * 2 + 0] + bias_sm[col];
                float v1 = acc[t][j][half * 2 + 1] + bias_sm[col + 1];
                if (MODE == 0) {
                    v0 = fmaxf(v0, 0.f); v1 = fmaxf(v1, 0.f);
                } else if (MODE == 1) {
                    float2 be = *(const float2*)(extra + (size_t)p * 128 + col);
                    float2 ga = *(const float2*)(extra + (size_t)p * 128 + 64 + col);
                    v0 = v0 * be.x + ga.x;
                    v1 = v1 * be.y + ga.y;
                } else { // MODE 3
                    float2 rs = *(const float2*)(extra + (size_t)p * 64 + col);
                    v0 = fmaxf(v0, 0.f) + rs.x;
                    v1 = fmaxf(v1, 0.f) + rs.y;
                }
                if (MODE == 3) {
                    *(float2*)(outf + (size_t)p * 64 + col) = make_float2(v0, v1);
                } else {
                    __half2 hv = __floats2half2_rn(v0, v1);
                    *(__half2*)(out16 + (size_t)p * 64 + col) = hv;
                }
            }
        }
    }
}

// ---------------- launch ----------------
extern "C" void kernel_launch(void* const* d_in, const int* in_sizes, int n_in,
                              void* d_out, int out_size)
{
    const float* feats = (const float*)d_in[0];
    const float* cond  = (const float*)d_in[1];
    const float* W1a   = (const float*)d_in[2];
    const float* b1a   = (const float*)d_in[3];
    const float* W1b   = (const float*)d_in[4];
    const float* b1b   = (const float*)d_in[5];
    const float* W2a   = (const float*)d_in[6];
    const float* b2a   = (const float*)d_in[7];
    const float* W2b   = (const float*)d_in[8];
    const float* b2b   = (const float*)d_in[9];
    const int*   nbr   = (const int*)d_in[10];

    int P = in_sizes[0] / N_CH;
    float* out = (float*)d_out;

    fp16 *x16, *a16, *b16, *wh;
    cudaGetSymbolAddress((void**)&x16, g_x16);
    cudaGetSymbolAddress((void**)&a16, g_a16);
    cudaGetSymbolAddress((void**)&b16, g_b16);
    cudaGetSymbolAddress((void**)&wh,  g_wh);

    cudaFuncSetAttribute(conv_mma<0>, cudaFuncAttributeMaxDynamicSharedMemorySize, SMEM_TOTAL);
    cudaFuncSetAttribute(conv_mma<1>, cudaFuncAttributeMaxDynamicSharedMemorySize, SMEM_TOTAL);
    cudaFuncSetAttribute(conv_mma<3>, cudaFuncAttributeMaxDynamicSharedMemorySize, SMEM_TOTAL);

    {
        dim3 g((27 * 4096 + 255) / 256, 4);
        prep_weights<<<g, 256>>>(W1a, W1b, W2a, W2b, wh);
    }
    prep_feats<<<(P * N_CH + 255) / 256, 256>>>(feats, x16, P * N_CH);

    const size_t LW = (size_t)27 * 4096;
    int grid = (P + 127) / 128;
    conv_mma<0><<<grid, 256, SMEM_TOTAL>>>(x16, nbr, wh + 0 * LW,
                                           b1a, nullptr, nullptr, a16, P);
    conv_mma<1><<<grid, 256, SMEM_TOTAL>>>(a16, nbr, wh + 1 * LW,
                                           b1b, cond, nullptr, b16, P);
    conv_mma<0><<<grid, 256, SMEM_TOTAL>>>(b16, nbr, wh + 2 * LW,
                                           b2a, nullptr, nullptr, a16, P);
    conv_mma<3><<<grid, 256, SMEM_TOTAL>>>(a16, nbr, wh + 3 * LW,
                                           b2b, feats, out, nullptr, P);
}